// round 1
// baseline (speedup 1.0000x reference)
#include <cuda_runtime.h>

#define NMAX 100000
#define EMAX 1000000

// ---------------- scratch (no allocations allowed) ----------------
__device__ float g_h1[NMAX * 64];    // lin1 output
__device__ float g_agg1[NMAX * 64];  // aggregation target layer 1
__device__ float g_h2[NMAX * 40];    // lin2 output (after mid-MLP)
__device__ float g_agg2[NMAX * 40];  // aggregation target layer 2
__device__ int   g_idx32;            // 1 if edge_index is int32, 0 if int64

__device__ __forceinline__ void red_add_f4(float* p, float4 v) {
    asm volatile("red.global.add.v4.f32 [%0], {%1,%2,%3,%4};"
                 :: "l"(p), "f"(v.x), "f"(v.y), "f"(v.z), "f"(v.w)
                 : "memory");
}

// ---------------- dtype probe: int64 vs int32 edge_index ----------------
// If data is int32, reading as int64 packs pairs (a | b<<32); with b uniform in
// [0,1e5) the value exceeds N except with prob 1e-5 per sample. 64 samples.
__global__ void detect_idx_kernel(const long long* __restrict__ idx, int E, long long N) {
    if (blockIdx.x == 0 && threadIdx.x == 0) {
        int is32 = 0;
        int nc = E < 64 ? E : 64;
        for (int i = 0; i < nc; i++) {
            long long v = idx[i];
            if (v < 0 || v >= N) { is32 = 1; break; }
        }
        g_idx32 = is32;
    }
}

// ---------------- K1: h = x @ W1^T + b1  (128 -> 64), write h1 and agg1 ----------------
// 128 threads, 64 nodes/block. Thread computes 8 nodes x 4 feats (32 acc).
// dyn smem: sW[128*65] (k-major, padded) + sx[64*129] (node-major, padded)
__global__ void lin1_kernel(const float* __restrict__ x, const float* __restrict__ W,
                            const float* __restrict__ b, int N) {
    extern __shared__ float sm[];
    float* sW = sm;             // sW[k*65 + f], k<128, f<64
    float* sx = sm + 128 * 65;  // sx[n*129 + k], n<64, k<128
    int t = threadIdx.x;

    for (int i = t; i < 64 * 128; i += 128) {
        int f = i >> 7, k = i & 127;          // W row-major [64][128]
        sW[k * 65 + f] = W[i];
    }
    int n0 = blockIdx.x * 64;
    for (int i = t; i < 64 * 128; i += 128) {
        int n = i >> 7, k = i & 127;
        int gn = n0 + n;
        sx[n * 129 + k] = (gn < N) ? x[(long long)gn * 128 + k] : 0.f;
    }
    __syncthreads();

    int fq = (t & 15) * 4;
    int ng = (t >> 4) * 8;
    float acc[8][4];
#pragma unroll
    for (int m = 0; m < 8; m++)
#pragma unroll
        for (int j = 0; j < 4; j++) acc[m][j] = 0.f;

#pragma unroll 4
    for (int k = 0; k < 128; k++) {
        float w0 = sW[k * 65 + fq + 0];
        float w1 = sW[k * 65 + fq + 1];
        float w2 = sW[k * 65 + fq + 2];
        float w3 = sW[k * 65 + fq + 3];
#pragma unroll
        for (int m = 0; m < 8; m++) {
            float xv = sx[(ng + m) * 129 + k];
            acc[m][0] += xv * w0; acc[m][1] += xv * w1;
            acc[m][2] += xv * w2; acc[m][3] += xv * w3;
        }
    }
    float b0 = __ldg(b + fq + 0), b1 = __ldg(b + fq + 1);
    float b2 = __ldg(b + fq + 2), b3 = __ldg(b + fq + 3);
#pragma unroll
    for (int m = 0; m < 8; m++) {
        int gn = n0 + ng + m;
        if (gn < N) {
            float4 v = make_float4(acc[m][0] + b0, acc[m][1] + b1,
                                   acc[m][2] + b2, acc[m][3] + b3);
            *(float4*)(g_h1   + (long long)gn * 64 + fq) = v;
            *(float4*)(g_agg1 + (long long)gn * 64 + fq) = v;
        }
    }
}

// ---------------- K2: scatter layer 1 (64 feats = 16 quads per edge) ----------------
__global__ void scatter1_kernel(const long long* __restrict__ idx, int E) {
    long long q = (long long)blockIdx.x * blockDim.x + threadIdx.x;
    if (q >= (long long)E * 16) return;
    int e = (int)(q >> 4);
    int c = ((int)q & 15) << 2;
    long long s, d;
    if (g_idx32) {
        const int* p = (const int*)idx;
        s = p[e]; d = p[E + e];
    } else {
        s = idx[e]; d = idx[E + e];
    }
    float4 v = __ldg((const float4*)(g_h1 + s * 64 + c));
    red_add_f4(g_agg1 + d * 64 + c, v);
}

// ---------------- K3: fused mid-MLP ----------------
// a = relu(agg1); b = relu(Wo1 a + bo1); h = relu(Wo2 b + bo2); h2 = W2l h + b2l
// 128 threads, 64 nodes/block, 3 chained stages through smem.
// dyn smem: sW1[64*65] + sW2[64*65] + sW3[64*40] + sA[64*65] + sB[64*65]
__global__ void mlp1_kernel(const float* __restrict__ Wo1, const float* __restrict__ bo1,
                            const float* __restrict__ Wo2, const float* __restrict__ bo2,
                            const float* __restrict__ W2l, const float* __restrict__ b2l,
                            int N) {
    extern __shared__ float sm[];
    float* sW1 = sm;                  // [k*65+f] k<64 f<64
    float* sW2 = sW1 + 64 * 65;
    float* sW3 = sW2 + 64 * 65;       // [k*40+f] k<64 f<40
    float* sA  = sW3 + 64 * 40;       // [n*65+k]
    float* sB  = sA  + 64 * 65;
    int t = threadIdx.x;

    for (int i = t; i < 64 * 64; i += 128) {
        int f = i >> 6, k = i & 63;
        sW1[k * 65 + f] = Wo1[i];
        sW2[k * 65 + f] = Wo2[i];
    }
    for (int i = t; i < 40 * 64; i += 128) {
        int f = i >> 6, k = i & 63;   // W2l row-major [40][64]
        sW3[k * 40 + f] = W2l[i];
    }
    int n0 = blockIdx.x * 64;
    for (int i = t; i < 64 * 64; i += 128) {
        int n = i >> 6, k = i & 63;
        int gn = n0 + n;
        float v = (gn < N) ? g_agg1[(long long)gn * 64 + k] : 0.f;
        sA[n * 65 + k] = fmaxf(v, 0.f);
    }
    __syncthreads();

    int fq = (t & 15) * 4;
    int ng = (t >> 4) * 8;

    // stage 1: sB = relu(sA @ Wo1^T + bo1)
    {
        float acc[8][4];
#pragma unroll
        for (int m = 0; m < 8; m++)
#pragma unroll
            for (int j = 0; j < 4; j++) acc[m][j] = 0.f;
#pragma unroll 4
        for (int k = 0; k < 64; k++) {
            float w0 = sW1[k * 65 + fq + 0];
            float w1 = sW1[k * 65 + fq + 1];
            float w2 = sW1[k * 65 + fq + 2];
            float w3 = sW1[k * 65 + fq + 3];
#pragma unroll
            for (int m = 0; m < 8; m++) {
                float xv = sA[(ng + m) * 65 + k];
                acc[m][0] += xv * w0; acc[m][1] += xv * w1;
                acc[m][2] += xv * w2; acc[m][3] += xv * w3;
            }
        }
        float c0 = __ldg(bo1 + fq + 0), c1 = __ldg(bo1 + fq + 1);
        float c2 = __ldg(bo1 + fq + 2), c3 = __ldg(bo1 + fq + 3);
#pragma unroll
        for (int m = 0; m < 8; m++) {
            sB[(ng + m) * 65 + fq + 0] = fmaxf(acc[m][0] + c0, 0.f);
            sB[(ng + m) * 65 + fq + 1] = fmaxf(acc[m][1] + c1, 0.f);
            sB[(ng + m) * 65 + fq + 2] = fmaxf(acc[m][2] + c2, 0.f);
            sB[(ng + m) * 65 + fq + 3] = fmaxf(acc[m][3] + c3, 0.f);
        }
    }
    __syncthreads();

    // stage 2: sA = relu(sB @ Wo2^T + bo2)   (outer relu between convs)
    {
        float acc[8][4];
#pragma unroll
        for (int m = 0; m < 8; m++)
#pragma unroll
            for (int j = 0; j < 4; j++) acc[m][j] = 0.f;
#pragma unroll 4
        for (int k = 0; k < 64; k++) {
            float w0 = sW2[k * 65 + fq + 0];
            float w1 = sW2[k * 65 + fq + 1];
            float w2 = sW2[k * 65 + fq + 2];
            float w3 = sW2[k * 65 + fq + 3];
#pragma unroll
            for (int m = 0; m < 8; m++) {
                float xv = sB[(ng + m) * 65 + k];
                acc[m][0] += xv * w0; acc[m][1] += xv * w1;
                acc[m][2] += xv * w2; acc[m][3] += xv * w3;
            }
        }
        float c0 = __ldg(bo2 + fq + 0), c1 = __ldg(bo2 + fq + 1);
        float c2 = __ldg(bo2 + fq + 2), c3 = __ldg(bo2 + fq + 3);
        __syncthreads();   // sA still being read above? No: stage2 reads sB only. Safe point before overwrite.
#pragma unroll
        for (int m = 0; m < 8; m++) {
            sA[(ng + m) * 65 + fq + 0] = fmaxf(acc[m][0] + c0, 0.f);
            sA[(ng + m) * 65 + fq + 1] = fmaxf(acc[m][1] + c1, 0.f);
            sA[(ng + m) * 65 + fq + 2] = fmaxf(acc[m][2] + c2, 0.f);
            sA[(ng + m) * 65 + fq + 3] = fmaxf(acc[m][3] + c3, 0.f);
        }
    }
    __syncthreads();

    // stage 3: h2 = sA @ W2l^T + b2l  (64 -> 40), write g_h2 and g_agg2
    if ((t & 15) < 10) {
        float acc[8][4];
#pragma unroll
        for (int m = 0; m < 8; m++)
#pragma unroll
            for (int j = 0; j < 4; j++) acc[m][j] = 0.f;
#pragma unroll 4
        for (int k = 0; k < 64; k++) {
            float w0 = sW3[k * 40 + fq + 0];
            float w1 = sW3[k * 40 + fq + 1];
            float w2 = sW3[k * 40 + fq + 2];
            float w3 = sW3[k * 40 + fq + 3];
#pragma unroll
            for (int m = 0; m < 8; m++) {
                float xv = sA[(ng + m) * 65 + k];
                acc[m][0] += xv * w0; acc[m][1] += xv * w1;
                acc[m][2] += xv * w2; acc[m][3] += xv * w3;
            }
        }
        float c0 = __ldg(b2l + fq + 0), c1 = __ldg(b2l + fq + 1);
        float c2 = __ldg(b2l + fq + 2), c3 = __ldg(b2l + fq + 3);
#pragma unroll
        for (int m = 0; m < 8; m++) {
            int gn = n0 + ng + m;
            if (gn < N) {
                float4 v = make_float4(acc[m][0] + c0, acc[m][1] + c1,
                                       acc[m][2] + c2, acc[m][3] + c3);
                *(float4*)(g_h2   + (long long)gn * 40 + fq) = v;
                *(float4*)(g_agg2 + (long long)gn * 40 + fq) = v;
            }
        }
    }
}

// ---------------- K4: scatter layer 2 (40 feats = 10 quads per edge) ----------------
__global__ void scatter2_kernel(const long long* __restrict__ idx, int E) {
    long long q = (long long)blockIdx.x * blockDim.x + threadIdx.x;
    if (q >= (long long)E * 10) return;
    int e = (int)(q / 10);
    int c = ((int)(q - (long long)e * 10)) * 4;
    long long s, d;
    if (g_idx32) {
        const int* p = (const int*)idx;
        s = p[e]; d = p[E + e];
    } else {
        s = idx[e]; d = idx[E + e];
    }
    float4 v = __ldg((const float4*)(g_h2 + s * 40 + c));
    red_add_f4(g_agg2 + d * 40 + c, v);
}

// ---------------- K5: final MLP ----------------
// a = relu(agg2); b = relu(W2o1 a + b2o1); out = W2o2 b + b2o2
__global__ void mlp2_kernel(const float* __restrict__ Wo1, const float* __restrict__ bo1,
                            const float* __restrict__ Wo2, const float* __restrict__ bo2,
                            float* __restrict__ out, int N) {
    __shared__ float sW1[40 * 40];   // [k*40+f]
    __shared__ float sW2[40 * 40];
    __shared__ float sA[64 * 41];    // [n*41+k] k<40
    __shared__ float sB[64 * 41];
    int t = threadIdx.x;

    for (int i = t; i < 1600; i += 128) {
        int f = i / 40, k = i - f * 40;
        sW1[k * 40 + f] = Wo1[i];
        sW2[k * 40 + f] = Wo2[i];
    }
    int n0 = blockIdx.x * 64;
    for (int i = t; i < 64 * 40; i += 128) {
        int n = i / 40, k = i - n * 40;
        int gn = n0 + n;
        float v = (gn < N) ? g_agg2[(long long)gn * 40 + k] : 0.f;
        sA[n * 41 + k] = fmaxf(v, 0.f);
    }
    __syncthreads();

    int fq = (t & 15) * 4;
    int ng = (t >> 4) * 8;

    if ((t & 15) < 10) {
        float acc[8][4];
#pragma unroll
        for (int m = 0; m < 8; m++)
#pragma unroll
            for (int j = 0; j < 4; j++) acc[m][j] = 0.f;
#pragma unroll 4
        for (int k = 0; k < 40; k++) {
            float w0 = sW1[k * 40 + fq + 0];
            float w1 = sW1[k * 40 + fq + 1];
            float w2 = sW1[k * 40 + fq + 2];
            float w3 = sW1[k * 40 + fq + 3];
#pragma unroll
            for (int m = 0; m < 8; m++) {
                float xv = sA[(ng + m) * 41 + k];
                acc[m][0] += xv * w0; acc[m][1] += xv * w1;
                acc[m][2] += xv * w2; acc[m][3] += xv * w3;
            }
        }
        float c0 = __ldg(bo1 + fq + 0), c1 = __ldg(bo1 + fq + 1);
        float c2 = __ldg(bo1 + fq + 2), c3 = __ldg(bo1 + fq + 3);
#pragma unroll
        for (int m = 0; m < 8; m++) {
            sB[(ng + m) * 41 + fq + 0] = fmaxf(acc[m][0] + c0, 0.f);
            sB[(ng + m) * 41 + fq + 1] = fmaxf(acc[m][1] + c1, 0.f);
            sB[(ng + m) * 41 + fq + 2] = fmaxf(acc[m][2] + c2, 0.f);
            sB[(ng + m) * 41 + fq + 3] = fmaxf(acc[m][3] + c3, 0.f);
        }
    }
    __syncthreads();

    if ((t & 15) < 10) {
        float acc[8][4];
#pragma unroll
        for (int m = 0; m < 8; m++)
#pragma unroll
            for (int j = 0; j < 4; j++) acc[m][j] = 0.f;
#pragma unroll 4
        for (int k = 0; k < 40; k++) {
            float w0 = sW2[k * 40 + fq + 0];
            float w1 = sW2[k * 40 + fq + 1];
            float w2 = sW2[k * 40 + fq + 2];
            float w3 = sW2[k * 40 + fq + 3];
#pragma unroll
            for (int m = 0; m < 8; m++) {
                float xv = sB[(ng + m) * 41 + k];
                acc[m][0] += xv * w0; acc[m][1] += xv * w1;
                acc[m][2] += xv * w2; acc[m][3] += xv * w3;
            }
        }
        float c0 = __ldg(bo2 + fq + 0), c1 = __ldg(bo2 + fq + 1);
        float c2 = __ldg(bo2 + fq + 2), c3 = __ldg(bo2 + fq + 3);
#pragma unroll
        for (int m = 0; m < 8; m++) {
            int gn = n0 + ng + m;
            if (gn < N) {
                out[(long long)gn * 40 + fq + 0] = acc[m][0] + c0;
                out[(long long)gn * 40 + fq + 1] = acc[m][1] + c1;
                out[(long long)gn * 40 + fq + 2] = acc[m][2] + c2;
                out[(long long)gn * 40 + fq + 3] = acc[m][3] + c3;
            }
        }
    }
}

// ---------------- launch ----------------
extern "C" void kernel_launch(void* const* d_in, const int* in_sizes, int n_in,
                              void* d_out, int out_size) {
    const float*     x   = (const float*)d_in[0];
    const long long* idx = (const long long*)d_in[1];
    const float* w1_lin = (const float*)d_in[2];
    const float* b1_lin = (const float*)d_in[3];
    const float* w1_o1  = (const float*)d_in[4];
    const float* b1_o1  = (const float*)d_in[5];
    const float* w1_o2  = (const float*)d_in[6];
    const float* b1_o2  = (const float*)d_in[7];
    const float* w2_lin = (const float*)d_in[8];
    const float* b2_lin = (const float*)d_in[9];
    const float* w2_o1  = (const float*)d_in[10];
    const float* b2_o1  = (const float*)d_in[11];
    const float* w2_o2  = (const float*)d_in[12];
    const float* b2_o2  = (const float*)d_in[13];
    float* out = (float*)d_out;

    int N = in_sizes[0] / 128;
    int E = in_sizes[1] / 2;

    // dynamic smem opt-in (idempotent, host-side config; no allocation)
    size_t smem_lin1 = (size_t)(128 * 65 + 64 * 129) * sizeof(float);
    size_t smem_mlp1 = (size_t)(64 * 65 * 2 + 64 * 40 + 64 * 65 * 2) * sizeof(float);
    cudaFuncSetAttribute(lin1_kernel, cudaFuncAttributeMaxDynamicSharedMemorySize, (int)smem_lin1);
    cudaFuncSetAttribute(mlp1_kernel, cudaFuncAttributeMaxDynamicSharedMemorySize, (int)smem_mlp1);

    int nodeBlocks = (N + 63) / 64;

    detect_idx_kernel<<<1, 32>>>(idx, E, (long long)N);

    lin1_kernel<<<nodeBlocks, 128, smem_lin1>>>(x, w1_lin, b1_lin, N);

    long long q1 = (long long)E * 16;
    scatter1_kernel<<<(int)((q1 + 255) / 256), 256>>>(idx, E);

    mlp1_kernel<<<nodeBlocks, 128, smem_mlp1>>>(w1_o1, b1_o1, w1_o2, b1_o2,
                                                w2_lin, b2_lin, N);

    long long q2 = (long long)E * 10;
    scatter2_kernel<<<(int)((q2 + 255) / 256), 256>>>(idx, E);

    mlp2_kernel<<<nodeBlocks, 128>>>(w2_o1, b2_o1, w2_o2, b2_o2, out, N);
}